// round 10
// baseline (speedup 1.0000x reference)
#include <cuda_runtime.h>

// DeepFilterNet DF coef op, GB300 — R10: R9 + __ldcg fast loads (L1 bypass)
// + center-tap (i==2) reuse in the DF path.
//
// spec  : [B=32, 1, T=1000, F=481, 2] f32
// coefs : [B, T, 5, 96, 2] f32
// alpha : [B, T, 1] f32
// out   : same as spec; first 96 bins = 5-tap complex FIR blended with alpha.
//
// Policy state (all A/B-tested): loads/stores default at L2; fast-path loads
// bypass L1 (__ldcg) since the 196MB stream has zero L1 reuse.

#define B_DIM 32
#define T_DIM 1000
#define F_DIM 481
#define F_DF 96
#define ORDER 5

#define NROWPAIR 16000                 // 32000 rows / 2
#define NSLOW    (NROWPAIR * 97)       // 1,552,000 pairs
#define NFAST    (NROWPAIR * 384)      // 6,144,000 pairs
#define TPB      256
#define SLOW_BLOCKS ((NSLOW + TPB - 1) / TPB)     // 6063
#define FAST_BLOCKS (NFAST / (2 * TPB))           // 12000 (exact)

__device__ __forceinline__ float2 df_elem(
    const float2* __restrict__ spec,
    const float2* __restrict__ coefs,
    const float*  __restrict__ alpha,
    int bt, int f, float2 s)
{
    int t = bt % T_DIM;
    const float2* cptr = coefs + (size_t)bt * (ORDER * F_DF) + f;

    float re = 0.0f, im = 0.0f;
    #pragma unroll
    for (int i = 0; i < ORDER; i++) {
        float2 w;
        if (i == 2) {
            w = s;                                // center tap == this element
        } else {
            int tt = t + i - 2;                   // ORDER - LOOKAHEAD - 1 = 2
            w = make_float2(0.0f, 0.0f);
            if (tt >= 0 && tt < T_DIM)
                w = spec[(size_t)(bt + i - 2) * F_DIM + f];
        }
        float2 c = cptr[(size_t)i * F_DF];
        re = fmaf(w.x, c.x, re);
        re = fmaf(-w.y, c.y, re);
        im = fmaf(w.y, c.x, im);
        im = fmaf(w.x, c.y, im);
    }

    float a  = alpha[bt];
    float na = 1.0f - a;
    return make_float2(fmaf(re, a, s.x * na), fmaf(im, a, s.y * na));
}

// map fast-path linear index g -> pair index p
__device__ __forceinline__ int fast_map(int g)
{
    int rp = g / 384;
    int k  = g - rp * 384;
    // k <  192: even row, p = 481*rp + 48 + k
    // k >= 192: odd  row, p = 481*rp + 97 + k
    return 481 * rp + k + ((k < 192) ? 48 : 97);
}

__global__ void __launch_bounds__(TPB) df_coef_kernel(
    const float4* __restrict__ spec4,
    const float2* __restrict__ spec2,
    const float2* __restrict__ coefs,
    const float*  __restrict__ alpha,
    float4* __restrict__ out4)
{
    if (blockIdx.x >= SLOW_BLOCKS) {
        // ---- FAST: passthrough copy, 2 pairs/thread, loads front-batched ----
        int fb = blockIdx.x - SLOW_BLOCKS;
        int g0 = fb * (2 * TPB) + threadIdx.x;     // < NFAST guaranteed
        int g1 = g0 + TPB;
        int p0 = fast_map(g0);
        int p1 = fast_map(g1);
        float4 v0 = __ldcg(&spec4[p0]);            // L2-cached, L1-bypass
        float4 v1 = __ldcg(&spec4[p1]);
        out4[p0] = v0;
        out4[p1] = v1;
        return;
    }

    // ---- SLOW: pairs containing at least one DF bin ----
    int s = blockIdx.x * TPB + threadIdx.x;
    if (s >= NSLOW) return;
    int rp = s / 97;
    int k  = s - rp * 97;
    int r0 = 2 * rp;

    int p, bt0, f0, bt1, f1;
    if (k < 48) {                 // even row, both elements DF
        p = 481 * rp + k;
        bt0 = r0;     f0 = 2 * k;
        bt1 = r0;     f1 = f0 + 1;
    } else if (k < 96) {          // odd row
        p = 481 * rp + k + 193;
        bt0 = r0 + 1; f0 = 2 * (k - 48) + 1;
        bt1 = r0 + 1; f1 = f0 + 1;          // f1 == 96 when k == 95 (pass)
    } else {                      // boundary pair: (r0, 480) | (r0+1, 0)
        p = 481 * rp + 240;
        bt0 = r0;     f0 = 480;             // passthrough
        bt1 = r0 + 1; f1 = 0;               // DF
    }

    float4 s4 = spec4[p];
    float2 e0 = make_float2(s4.x, s4.y);
    float2 e1 = make_float2(s4.z, s4.w);

    float2 r0v = (f0 < F_DF) ? df_elem(spec2, coefs, alpha, bt0, f0, e0) : e0;
    float2 r1v = (f1 < F_DF) ? df_elem(spec2, coefs, alpha, bt1, f1, e1) : e1;

    out4[p] = make_float4(r0v.x, r0v.y, r1v.x, r1v.y);
}

extern "C" void kernel_launch(void* const* d_in, const int* in_sizes, int n_in,
                              void* d_out, int out_size)
{
    const float4* spec4 = (const float4*)d_in[0];
    const float2* spec2 = (const float2*)d_in[0];
    const float2* coefs = (const float2*)d_in[1];
    const float*  alpha = (const float*)d_in[2];

    df_coef_kernel<<<SLOW_BLOCKS + FAST_BLOCKS, TPB>>>(
        spec4, spec2, coefs, alpha, (float4*)d_out);
}

// round 11
// speedup vs baseline: 1.0058x; 1.0058x over previous
#include <cuda_runtime.h>

// DeepFilterNet DF coef op, GB300 — R11 (final candidate): consolidated best.
//   * float4 pair decomposition (always 16B-aligned; 2 complex elems/pair)
//   * exact block-role split: 6063 DF blocks first, 12000 copy blocks after
//   * fast path: ILP=2, front-batched loads (concurrency-saturating, R6/R7)
//   * all loads/stores DEFAULT cache policy (A/B: beat ldcs, stcs, ldcg)
//   * center tap (i==2) reused from the already-loaded element
//
// Measured regime: DRAM ~78% (6.2 TB/s), HBM mixed-R/W turnaround bound;
// all other pipes <50%. Logical traffic (369 MB) is minimal for this op.
//
// spec  : [B=32, 1, T=1000, F=481, 2] f32
// coefs : [B, T, 5, 96, 2] f32
// alpha : [B, T, 1] f32
// out   : same as spec; first 96 bins = 5-tap complex FIR blended with alpha.

#define B_DIM 32
#define T_DIM 1000
#define F_DIM 481
#define F_DF 96
#define ORDER 5

#define NROWPAIR 16000                 // 32000 rows / 2
#define NSLOW    (NROWPAIR * 97)       // 1,552,000 pairs
#define NFAST    (NROWPAIR * 384)      // 6,144,000 pairs
#define TPB      256
#define SLOW_BLOCKS ((NSLOW + TPB - 1) / TPB)     // 6063
#define FAST_BLOCKS (NFAST / (2 * TPB))           // 12000 (exact)

__device__ __forceinline__ float2 df_elem(
    const float2* __restrict__ spec,
    const float2* __restrict__ coefs,
    const float*  __restrict__ alpha,
    int bt, int f, float2 s)
{
    int t = bt % T_DIM;
    const float2* cptr = coefs + (size_t)bt * (ORDER * F_DF) + f;

    float re = 0.0f, im = 0.0f;
    #pragma unroll
    for (int i = 0; i < ORDER; i++) {
        float2 w;
        if (i == 2) {
            w = s;                                // center tap == this element
        } else {
            int tt = t + i - 2;                   // ORDER - LOOKAHEAD - 1 = 2
            w = make_float2(0.0f, 0.0f);
            if (tt >= 0 && tt < T_DIM)
                w = spec[(size_t)(bt + i - 2) * F_DIM + f];
        }
        float2 c = cptr[(size_t)i * F_DF];
        re = fmaf(w.x, c.x, re);
        re = fmaf(-w.y, c.y, re);
        im = fmaf(w.y, c.x, im);
        im = fmaf(w.x, c.y, im);
    }

    float a  = alpha[bt];
    float na = 1.0f - a;
    return make_float2(fmaf(re, a, s.x * na), fmaf(im, a, s.y * na));
}

// map fast-path linear index g -> pair index p
__device__ __forceinline__ int fast_map(int g)
{
    int rp = g / 384;
    int k  = g - rp * 384;
    // k <  192: even row, p = 481*rp + 48 + k
    // k >= 192: odd  row, p = 481*rp + 97 + k
    return 481 * rp + k + ((k < 192) ? 48 : 97);
}

__global__ void __launch_bounds__(TPB) df_coef_kernel(
    const float4* __restrict__ spec4,
    const float2* __restrict__ spec2,
    const float2* __restrict__ coefs,
    const float*  __restrict__ alpha,
    float4* __restrict__ out4)
{
    if (blockIdx.x >= SLOW_BLOCKS) {
        // ---- FAST: passthrough copy, 2 pairs/thread, loads front-batched ----
        int fb = blockIdx.x - SLOW_BLOCKS;
        int g0 = fb * (2 * TPB) + threadIdx.x;     // < NFAST guaranteed
        int g1 = g0 + TPB;
        int p0 = fast_map(g0);
        int p1 = fast_map(g1);
        float4 v0 = spec4[p0];
        float4 v1 = spec4[p1];
        out4[p0] = v0;
        out4[p1] = v1;
        return;
    }

    // ---- SLOW: pairs containing at least one DF bin ----
    int s = blockIdx.x * TPB + threadIdx.x;
    if (s >= NSLOW) return;
    int rp = s / 97;
    int k  = s - rp * 97;
    int r0 = 2 * rp;

    int p, bt0, f0, bt1, f1;
    if (k < 48) {                 // even row, both elements DF
        p = 481 * rp + k;
        bt0 = r0;     f0 = 2 * k;
        bt1 = r0;     f1 = f0 + 1;
    } else if (k < 96) {          // odd row
        p = 481 * rp + k + 193;
        bt0 = r0 + 1; f0 = 2 * (k - 48) + 1;
        bt1 = r0 + 1; f1 = f0 + 1;          // f1 == 96 when k == 95 (pass)
    } else {                      // boundary pair: (r0, 480) | (r0+1, 0)
        p = 481 * rp + 240;
        bt0 = r0;     f0 = 480;             // passthrough
        bt1 = r0 + 1; f1 = 0;               // DF
    }

    float4 s4 = spec4[p];
    float2 e0 = make_float2(s4.x, s4.y);
    float2 e1 = make_float2(s4.z, s4.w);

    float2 r0v = (f0 < F_DF) ? df_elem(spec2, coefs, alpha, bt0, f0, e0) : e0;
    float2 r1v = (f1 < F_DF) ? df_elem(spec2, coefs, alpha, bt1, f1, e1) : e1;

    out4[p] = make_float4(r0v.x, r0v.y, r1v.x, r1v.y);
}

extern "C" void kernel_launch(void* const* d_in, const int* in_sizes, int n_in,
                              void* d_out, int out_size)
{
    const float4* spec4 = (const float4*)d_in[0];
    const float2* spec2 = (const float2*)d_in[0];
    const float2* coefs = (const float2*)d_in[1];
    const float*  alpha = (const float*)d_in[2];

    df_coef_kernel<<<SLOW_BLOCKS + FAST_BLOCKS, TPB>>>(
        spec4, spec2, coefs, alpha, (float4*)d_out);
}

// round 12
// speedup vs baseline: 1.0514x; 1.0454x over previous
#include <cuda_runtime.h>

// DeepFilterNet DF coef op, GB300 — R12: R11 + Bresenham-interleaved block roles.
// Instead of [6063 slow][12000 fast] (which creates a slow-only head phase and
// a copy-only tail phase, each below the HBM mixed-traffic optimum), slow and
// fast blocks are interleaved uniformly: block b is "slow" iff
// floor((b+1)*S/T) > floor(b*S/T)  (S=6063, T=18063), giving each SM a steady
// mix of latency-bound DF blocks and bandwidth-bound copy blocks.
//
// spec  : [B=32, 1, T=1000, F=481, 2] f32
// coefs : [B, T, 5, 96, 2] f32
// alpha : [B, T, 1] f32
// out   : same as spec; first 96 bins = 5-tap complex FIR blended with alpha.

#define B_DIM 32
#define T_DIM 1000
#define F_DIM 481
#define F_DF 96
#define ORDER 5

#define NROWPAIR 16000                 // 32000 rows / 2
#define NSLOW    (NROWPAIR * 97)       // 1,552,000 pairs
#define NFAST    (NROWPAIR * 384)      // 6,144,000 pairs
#define TPB      256
#define SLOW_BLOCKS ((NSLOW + TPB - 1) / TPB)     // 6063
#define FAST_BLOCKS (NFAST / (2 * TPB))           // 12000 (exact)
#define TOT_BLOCKS  (SLOW_BLOCKS + FAST_BLOCKS)   // 18063

__device__ __forceinline__ float2 df_elem(
    const float2* __restrict__ spec,
    const float2* __restrict__ coefs,
    const float*  __restrict__ alpha,
    int bt, int f, float2 s)
{
    int t = bt % T_DIM;
    const float2* cptr = coefs + (size_t)bt * (ORDER * F_DF) + f;

    float re = 0.0f, im = 0.0f;
    #pragma unroll
    for (int i = 0; i < ORDER; i++) {
        float2 w;
        if (i == 2) {
            w = s;                                // center tap == this element
        } else {
            int tt = t + i - 2;                   // ORDER - LOOKAHEAD - 1 = 2
            w = make_float2(0.0f, 0.0f);
            if (tt >= 0 && tt < T_DIM)
                w = spec[(size_t)(bt + i - 2) * F_DIM + f];
        }
        float2 c = cptr[(size_t)i * F_DF];
        re = fmaf(w.x, c.x, re);
        re = fmaf(-w.y, c.y, re);
        im = fmaf(w.y, c.x, im);
        im = fmaf(w.x, c.y, im);
    }

    float a  = alpha[bt];
    float na = 1.0f - a;
    return make_float2(fmaf(re, a, s.x * na), fmaf(im, a, s.y * na));
}

// map fast-path linear index g -> pair index p
__device__ __forceinline__ int fast_map(int g)
{
    int rp = g / 384;
    int k  = g - rp * 384;
    // k <  192: even row, p = 481*rp + 48 + k
    // k >= 192: odd  row, p = 481*rp + 97 + k
    return 481 * rp + k + ((k < 192) ? 48 : 97);
}

__global__ void __launch_bounds__(TPB) df_coef_kernel(
    const float4* __restrict__ spec4,
    const float2* __restrict__ spec2,
    const float2* __restrict__ coefs,
    const float*  __restrict__ alpha,
    float4* __restrict__ out4)
{
    // Bresenham role decode: q0/q1 fit in 32 bits (18063*6063 < 2^31).
    const int b  = blockIdx.x;
    const int q0 = (int)(((long long)b       * SLOW_BLOCKS) / TOT_BLOCKS);
    const int q1 = (int)(((long long)(b + 1) * SLOW_BLOCKS) / TOT_BLOCKS);

    if (q1 == q0) {
        // ---- FAST: passthrough copy, 2 pairs/thread, loads front-batched ----
        int fb = b - q0;                           // fast block id, 0..11999
        int g0 = fb * (2 * TPB) + threadIdx.x;     // < NFAST guaranteed
        int g1 = g0 + TPB;
        int p0 = fast_map(g0);
        int p1 = fast_map(g1);
        float4 v0 = spec4[p0];
        float4 v1 = spec4[p1];
        out4[p0] = v0;
        out4[p1] = v1;
        return;
    }

    // ---- SLOW: pairs containing at least one DF bin ----
    int s = q0 * TPB + threadIdx.x;                // slow block id = q0
    if (s >= NSLOW) return;
    int rp = s / 97;
    int k  = s - rp * 97;
    int r0 = 2 * rp;

    int p, bt0, f0, bt1, f1;
    if (k < 48) {                 // even row, both elements DF
        p = 481 * rp + k;
        bt0 = r0;     f0 = 2 * k;
        bt1 = r0;     f1 = f0 + 1;
    } else if (k < 96) {          // odd row
        p = 481 * rp + k + 193;
        bt0 = r0 + 1; f0 = 2 * (k - 48) + 1;
        bt1 = r0 + 1; f1 = f0 + 1;          // f1 == 96 when k == 95 (pass)
    } else {                      // boundary pair: (r0, 480) | (r0+1, 0)
        p = 481 * rp + 240;
        bt0 = r0;     f0 = 480;             // passthrough
        bt1 = r0 + 1; f1 = 0;               // DF
    }

    float4 s4 = spec4[p];
    float2 e0 = make_float2(s4.x, s4.y);
    float2 e1 = make_float2(s4.z, s4.w);

    float2 r0v = (f0 < F_DF) ? df_elem(spec2, coefs, alpha, bt0, f0, e0) : e0;
    float2 r1v = (f1 < F_DF) ? df_elem(spec2, coefs, alpha, bt1, f1, e1) : e1;

    out4[p] = make_float4(r0v.x, r0v.y, r1v.x, r1v.y);
}

extern "C" void kernel_launch(void* const* d_in, const int* in_sizes, int n_in,
                              void* d_out, int out_size)
{
    const float4* spec4 = (const float4*)d_in[0];
    const float2* spec2 = (const float2*)d_in[0];
    const float2* coefs = (const float2*)d_in[1];
    const float*  alpha = (const float*)d_in[2];

    df_coef_kernel<<<TOT_BLOCKS, TPB>>>(
        spec4, spec2, coefs, alpha, (float4*)d_out);
}

// round 13
// speedup vs baseline: 1.0520x; 1.0006x over previous
#include <cuda_runtime.h>

// DeepFilterNet DF coef op, GB300 — R13: R12 (Bresenham role interleave)
// + fast-path ILP=4. Under interleave, slow blocks (2x duration) occupy ~half
// of resident warps, so fast warps need more per-warp MLP than the ILP=2
// setting tuned in the non-interleaved regime (R6/R7).
//
// spec  : [B=32, 1, T=1000, F=481, 2] f32
// coefs : [B, T, 5, 96, 2] f32
// alpha : [B, T, 1] f32
// out   : same as spec; first 96 bins = 5-tap complex FIR blended with alpha.

#define B_DIM 32
#define T_DIM 1000
#define F_DIM 481
#define F_DF 96
#define ORDER 5

#define NROWPAIR 16000                 // 32000 rows / 2
#define NSLOW    (NROWPAIR * 97)       // 1,552,000 pairs
#define NFAST    (NROWPAIR * 384)      // 6,144,000 pairs
#define TPB      256
#define FAST_ILP 4
#define SLOW_BLOCKS ((NSLOW + TPB - 1) / TPB)          // 6063
#define FAST_BLOCKS (NFAST / (FAST_ILP * TPB))          // 6000 (exact)
#define TOT_BLOCKS  (SLOW_BLOCKS + FAST_BLOCKS)         // 12063

__device__ __forceinline__ float2 df_elem(
    const float2* __restrict__ spec,
    const float2* __restrict__ coefs,
    const float*  __restrict__ alpha,
    int bt, int f, float2 s)
{
    int t = bt % T_DIM;
    const float2* cptr = coefs + (size_t)bt * (ORDER * F_DF) + f;

    float re = 0.0f, im = 0.0f;
    #pragma unroll
    for (int i = 0; i < ORDER; i++) {
        float2 w;
        if (i == 2) {
            w = s;                                // center tap == this element
        } else {
            int tt = t + i - 2;                   // ORDER - LOOKAHEAD - 1 = 2
            w = make_float2(0.0f, 0.0f);
            if (tt >= 0 && tt < T_DIM)
                w = spec[(size_t)(bt + i - 2) * F_DIM + f];
        }
        float2 c = cptr[(size_t)i * F_DF];
        re = fmaf(w.x, c.x, re);
        re = fmaf(-w.y, c.y, re);
        im = fmaf(w.y, c.x, im);
        im = fmaf(w.x, c.y, im);
    }

    float a  = alpha[bt];
    float na = 1.0f - a;
    return make_float2(fmaf(re, a, s.x * na), fmaf(im, a, s.y * na));
}

// map fast-path linear index g -> pair index p
__device__ __forceinline__ int fast_map(int g)
{
    int rp = g / 384;
    int k  = g - rp * 384;
    // k <  192: even row, p = 481*rp + 48 + k
    // k >= 192: odd  row, p = 481*rp + 97 + k
    return 481 * rp + k + ((k < 192) ? 48 : 97);
}

__global__ void __launch_bounds__(TPB) df_coef_kernel(
    const float4* __restrict__ spec4,
    const float2* __restrict__ spec2,
    const float2* __restrict__ coefs,
    const float*  __restrict__ alpha,
    float4* __restrict__ out4)
{
    // Bresenham role decode: slow iff floor((b+1)*S/T) > floor(b*S/T).
    const int b  = blockIdx.x;
    const int q0 = (int)(((long long)b       * SLOW_BLOCKS) / TOT_BLOCKS);
    const int q1 = (int)(((long long)(b + 1) * SLOW_BLOCKS) / TOT_BLOCKS);

    if (q1 == q0) {
        // ---- FAST: passthrough copy, 4 pairs/thread, loads front-batched ----
        int fb = b - q0;                                // fast block id, 0..5999
        int gb = fb * (FAST_ILP * TPB) + threadIdx.x;   // all in range (exact)

        int p[FAST_ILP];
        float4 v[FAST_ILP];
        #pragma unroll
        for (int j = 0; j < FAST_ILP; j++)
            p[j] = fast_map(gb + j * TPB);
        #pragma unroll
        for (int j = 0; j < FAST_ILP; j++)
            v[j] = spec4[p[j]];
        #pragma unroll
        for (int j = 0; j < FAST_ILP; j++)
            out4[p[j]] = v[j];
        return;
    }

    // ---- SLOW: pairs containing at least one DF bin ----
    int s = q0 * TPB + threadIdx.x;                     // slow block id = q0
    if (s >= NSLOW) return;
    int rp = s / 97;
    int k  = s - rp * 97;
    int r0 = 2 * rp;

    int p, bt0, f0, bt1, f1;
    if (k < 48) {                 // even row, both elements DF
        p = 481 * rp + k;
        bt0 = r0;     f0 = 2 * k;
        bt1 = r0;     f1 = f0 + 1;
    } else if (k < 96) {          // odd row
        p = 481 * rp + k + 193;
        bt0 = r0 + 1; f0 = 2 * (k - 48) + 1;
        bt1 = r0 + 1; f1 = f0 + 1;          // f1 == 96 when k == 95 (pass)
    } else {                      // boundary pair: (r0, 480) | (r0+1, 0)
        p = 481 * rp + 240;
        bt0 = r0;     f0 = 480;             // passthrough
        bt1 = r0 + 1; f1 = 0;               // DF
    }

    float4 s4 = spec4[p];
    float2 e0 = make_float2(s4.x, s4.y);
    float2 e1 = make_float2(s4.z, s4.w);

    float2 r0v = (f0 < F_DF) ? df_elem(spec2, coefs, alpha, bt0, f0, e0) : e0;
    float2 r1v = (f1 < F_DF) ? df_elem(spec2, coefs, alpha, bt1, f1, e1) : e1;

    out4[p] = make_float4(r0v.x, r0v.y, r1v.x, r1v.y);
}

extern "C" void kernel_launch(void* const* d_in, const int* in_sizes, int n_in,
                              void* d_out, int out_size)
{
    const float4* spec4 = (const float4*)d_in[0];
    const float2* spec2 = (const float2*)d_in[0];
    const float2* coefs = (const float2*)d_in[1];
    const float*  alpha = (const float*)d_in[2];

    df_coef_kernel<<<TOT_BLOCKS, TPB>>>(
        spec4, spec2, coefs, alpha, (float4*)d_out);
}